// round 11
// baseline (speedup 1.0000x reference)
#include <cuda_runtime.h>

#define T_DIM 4096
#define D_DIM 64
#define B_DIM 32
#define BLK 128
#define N_ITEMS 1024          // 131072 / BLK
#define GRID 888              // 6 blocks/SM * 148 SMs = exactly one wave

// ---- R1 per-thread body, byte-identical math (proven 18.9us) ----

template<int M>
__device__ __forceinline__ void transition(const float* __restrict__ F,
                                           float* __restrict__ C,
                                           const float* __restrict__ pmv,
                                           const float* __restrict__ dmb,
                                           int low, int up, float& res)
{
    float ft[M];
#pragma unroll
    for (int j = 0; j < M; j++) {
        float a = F[2 * j], b = F[2 * j + 1];
        C[j]  = 0.5f * (a + b);
        ft[j] = fmaf(a, pmv[2 * j], b * pmv[2 * j + 1]);
    }
    float suf = 0.f;
#pragma unroll
    for (int p = M - 1; p >= 1; p--) {
        const int W = M + p;
        float w = 0.f;
        if (W >= low && W < up) w = dmb[(W - 1) * T_DIM];
        float sc = 0.f;
#pragma unroll
        for (int j = p; j < M; j++) sc = fmaf(C[j], pmv[j + p], sc);
        res = fmaf(w, sc, res);
        suf += w;
        res = fmaf(ft[p - 1], suf, res);
    }
    {
        float w = 0.f;
        if (M >= low && M < up) w = dmb[(M - 1) * T_DIM];
        float sc = 0.f;
#pragma unroll
        for (int j = 0; j < M; j++) sc = fmaf(C[j], pmv[j], sc);
        res = fmaf(w, sc, res);
    }
}

__device__ __forceinline__ void transition32_load(const float* __restrict__ repb,
                                                  float* __restrict__ C,
                                                  const float* __restrict__ pmv,
                                                  const float* __restrict__ dmb,
                                                  int low, int up, float& res)
{
    constexpr int M = 32;
    float ft[M];
#pragma unroll
    for (int j = 0; j < M; j++) {
        float a = repb[(2 * j) * T_DIM];
        float b = repb[(2 * j + 1) * T_DIM];
        C[j]  = 0.5f * (a + b);
        ft[j] = fmaf(a, pmv[2 * j], b * pmv[2 * j + 1]);
    }
    float suf = 0.f;
#pragma unroll
    for (int p = M - 1; p >= 1; p--) {
        const int W = M + p;
        float w = 0.f;
        if (W >= low && W < up) w = dmb[(W - 1) * T_DIM];
        float sc = 0.f;
#pragma unroll
        for (int j = p; j < M; j++) sc = fmaf(C[j], pmv[j + p], sc);
        res = fmaf(w, sc, res);
        suf += w;
        res = fmaf(ft[p - 1], suf, res);
    }
    {
        float w = 0.f;
        if (M >= low && M < up) w = dmb[(M - 1) * T_DIM];
        float sc = 0.f;
#pragma unroll
        for (int j = 0; j < M; j++) sc = fmaf(C[j], pmv[j], sc);
        res = fmaf(w, sc, res);
    }
}

__device__ __forceinline__ void process_item(int gid,
                                             const float* __restrict__ rep,
                                             const float* __restrict__ dmask,
                                             const float* __restrict__ pmask,
                                             int low, int up,
                                             float* __restrict__ out)
{
    const int b = gid >> 12;                          // T = 4096
    const int t = gid & (T_DIM - 1);
    const int base = b * (D_DIM * T_DIM) + t;

    const float* __restrict__ pmb = pmask + base;
    const float* __restrict__ dmb = dmask + base;

    float pmv[64];
#pragma unroll
    for (int w = 0; w < 64; w++) pmv[w] = pmb[w * T_DIM];

    float res = 0.f;

    float L1[32]; transition32_load(rep + base, L1, pmv, dmb, low, up, res);
    float L2[16]; transition<16>(L1, L2, pmv, dmb, low, up, res);
    float L3[8];  transition<8>(L2, L3, pmv, dmb, low, up, res);
    float L4[4];  transition<4>(L3, L4, pmv, dmb, low, up, res);
    float L5[2];  transition<2>(L4, L5, pmv, dmb, low, up, res);

    const float x6 = 0.5f * (L5[0] + L5[1]);
    if (1 >= low && 1 < up) res = fmaf(dmb[0], x6 * pmv[0], res);

    out[gid] = res;
}

// Balanced single-wave launch: 888 blocks (6/SM on 148 SMs), grid-stride over
// 1024 items. The 136 double-item blocks scatter ~1 per SM, so per-SM work
// drops from max-8 to max-7 (in 128-thread units) vs the R1 launch config.
__global__ __launch_bounds__(BLK)
void ContextGenerator_34875134444049_kernel(const float* __restrict__ rep,
                                            const float* __restrict__ dmask,
                                            const float* __restrict__ pmask,
                                            const int* __restrict__ lowp,
                                            const int* __restrict__ upp,
                                            float* __restrict__ out)
{
    const int low = *lowp;
    const int up  = *upp;

    for (int item = blockIdx.x; item < N_ITEMS; item += GRID) {
        const int gid = item * BLK + threadIdx.x;
        process_item(gid, rep, dmask, pmask, low, up, out);
    }
}

extern "C" void kernel_launch(void* const* d_in, const int* in_sizes, int n_in,
                              void* d_out, int out_size)
{
    const float* rep   = (const float*)d_in[0];
    const float* dmask = (const float*)d_in[1];
    const float* pmask = (const float*)d_in[2];
    const int*   lowp  = (const int*)d_in[3];
    const int*   upp   = (const int*)d_in[4];
    float* out = (float*)d_out;

    ContextGenerator_34875134444049_kernel<<<GRID, BLK>>>(
        rep, dmask, pmask, lowp, upp, out);
}

// round 12
// speedup vs baseline: 1.2020x; 1.2020x over previous
#include <cuda_runtime.h>

#define T_DIM 4096
#define D_DIM 64
#define B_DIM 32
#define BLK 128

// R1 transition body + 4-deep software pipeline on the dm (duration-mask)
// loads: the only serial GMEM chain left. wbuf[4] indices are compile-time
// (full unroll) -> 4 registers, each load issued 4 iterations before use.
template<int M, int FS>
__device__ __forceinline__ void transition(const float* __restrict__ F,
                                           float* __restrict__ C,
                                           const float* __restrict__ pmv,
                                           const float* __restrict__ dmb,
                                           int low, int up, float& res)
{
    float ft[M];
#pragma unroll
    for (int j = 0; j < M; j++) {
        float a = F[(2 * j) * FS], b = F[(2 * j + 1) * FS];
        C[j]  = 0.5f * (a + b);
        ft[j] = fmaf(a, pmv[2 * j], b * pmv[2 * j + 1]);
    }

    // dm pipeline prologue: preload w for p = M-1 .. M-4 (batched LDGs)
    float wbuf[4];
#pragma unroll
    for (int i = 0; i < (M < 4 ? M : 4); i++) {
        const int p = M - 1 - i;
        const int W = M + p;
        wbuf[p & 3] = (W >= low && W < up) ? dmb[(W - 1) * T_DIM] : 0.f;
    }

    float suf = 0.f;
#pragma unroll
    for (int p = M - 1; p >= 1; p--) {
        const float w = wbuf[p & 3];
        if (p - 4 >= 0) {   // issue load 4 iterations ahead of use
            const int Wn = M + (p - 4);
            wbuf[(p - 4) & 3] = (Wn >= low && Wn < up) ? dmb[(Wn - 1) * T_DIM] : 0.f;
        }
        float sc = 0.f;
#pragma unroll
        for (int j = p; j < M; j++) sc = fmaf(C[j], pmv[j + p], sc);
        res = fmaf(w, sc, res);
        suf += w;
        res = fmaf(ft[p - 1], suf, res);
    }
    {   // p = 0: exact window W = M
        const float w = wbuf[0];
        float sc = 0.f;
#pragma unroll
        for (int j = 0; j < M; j++) sc = fmaf(C[j], pmv[j], sc);
        res = fmaf(w, sc, res);
    }
}

__global__ __launch_bounds__(BLK)
void ContextGenerator_34875134444049_kernel(const float* __restrict__ rep,
                                            const float* __restrict__ dmask,
                                            const float* __restrict__ pmask,
                                            const int* __restrict__ lowp,
                                            const int* __restrict__ upp,
                                            float* __restrict__ out)
{
    const int gid = blockIdx.x * BLK + threadIdx.x;   // 0 .. B*T-1
    const int b = gid >> 12;                          // T = 4096
    const int t = gid & (T_DIM - 1);
    const int base = b * (D_DIM * T_DIM) + t;

    const int low = *lowp;
    const int up  = *upp;

    const float* __restrict__ pmb = pmask + base;
    const float* __restrict__ dmb = dmask + base;

    float pmv[64];
#pragma unroll
    for (int w = 0; w < 64; w++) pmv[w] = pmb[w * T_DIM];

    float res = 0.f;

    float L1[32]; transition<32, T_DIM>(rep + base, L1, pmv, dmb, low, up, res);
    float L2[16]; transition<16, 1>(L1, L2, pmv, dmb, low, up, res);
    float L3[8];  transition<8, 1>(L2, L3, pmv, dmb, low, up, res);
    float L4[4];  transition<4, 1>(L3, L4, pmv, dmb, low, up, res);
    float L5[2];  transition<2, 1>(L4, L5, pmv, dmb, low, up, res);

    // W = 1: d = deepest level (single element)
    const float x6 = 0.5f * (L5[0] + L5[1]);
    if (1 >= low && 1 < up) res = fmaf(dmb[0], x6 * pmv[0], res);

    out[gid] = res;   // [B, 1, T] flat = gid
}

extern "C" void kernel_launch(void* const* d_in, const int* in_sizes, int n_in,
                              void* d_out, int out_size)
{
    const float* rep   = (const float*)d_in[0];
    const float* dmask = (const float*)d_in[1];
    const float* pmask = (const float*)d_in[2];
    const int*   lowp  = (const int*)d_in[3];
    const int*   upp   = (const int*)d_in[4];
    float* out = (float*)d_out;

    const int total = B_DIM * T_DIM;           // 131072
    ContextGenerator_34875134444049_kernel<<<total / BLK, BLK>>>(
        rep, dmask, pmask, lowp, upp, out);
}

// round 13
// speedup vs baseline: 1.3636x; 1.1345x over previous
#include <cuda_runtime.h>

#define T_DIM 4096
#define D_DIM 64
#define B_DIM 32
#define BLK 128
#define TP   (T_DIM / 2)        // 2048 point-pairs per batch row (u64 units)

typedef unsigned long long u64;   // two packed fp32 lanes (t, t+1)

__device__ __forceinline__ u64 fma2(u64 a, u64 b, u64 c) {
    u64 d; asm("fma.rn.f32x2 %0, %1, %2, %3;" : "=l"(d) : "l"(a), "l"(b), "l"(c)); return d;
}
__device__ __forceinline__ u64 mul2(u64 a, u64 b) {
    u64 d; asm("mul.rn.f32x2 %0, %1, %2;" : "=l"(d) : "l"(a), "l"(b)); return d;
}
__device__ __forceinline__ u64 add2(u64 a, u64 b) {
    u64 d; asm("add.rn.f32x2 %0, %1, %2;" : "=l"(d) : "l"(a), "l"(b)); return d;
}
#define HALF2 0x3F0000003F000000ULL   // {0.5f, 0.5f}

// Fused pyramid transition on packed lanes: fine F[2M] (u64 stride FS) ->
// coarse C[M], windows W = M .. 2M-1. R2-fused C build (each fine element
// read once) + R12 4-deep dm pipeline. DS = dm u64 row stride.
template<int M, int FS, int DS>
__device__ __forceinline__ void transition(const u64* __restrict__ F,
                                           u64* __restrict__ C,
                                           const u64* __restrict__ pmv,
                                           const u64* __restrict__ dmb,
                                           int low, int up, u64& res)
{
    C[M - 1] = mul2(HALF2, add2(F[(2 * M - 2) * FS], F[(2 * M - 1) * FS]));

    u64 wbuf[4];
#pragma unroll
    for (int i = 0; i < (M < 4 ? M : 4); i++) {
        const int p = M - 1 - i;
        const int W = M + p;
        wbuf[p & 3] = (W >= low && W < up) ? dmb[(W - 1) * DS] : 0ULL;
    }

    u64 suf = 0ULL;
#pragma unroll
    for (int p = M - 1; p >= 1; p--) {
        const u64 w = wbuf[p & 3];
        if (p - 4 >= 0) {
            const int Wn = M + (p - 4);
            wbuf[(p - 4) & 3] = (Wn >= low && Wn < up) ? dmb[(Wn - 1) * DS] : 0ULL;
        }
        u64 sc = 0ULL;
#pragma unroll
        for (int j = p; j < M; j++) sc = fma2(C[j], pmv[j + p], sc);
        res = fma2(w, sc, res);
        suf = add2(suf, w);
        const u64 a = F[(2 * p - 2) * FS], b = F[(2 * p - 1) * FS];
        res = fma2(fma2(a, pmv[2 * p - 2], mul2(b, pmv[2 * p - 1])), suf, res);
        C[p - 1] = mul2(HALF2, add2(a, b));
    }
    {   // p = 0: exact window W = M
        const u64 w0 = wbuf[0];
        u64 sc = 0ULL;
#pragma unroll
        for (int j = 0; j < M; j++) sc = fma2(C[j], pmv[j], sc);
        res = fma2(w0, sc, res);
    }
}

__global__ __launch_bounds__(BLK)
void ContextGenerator_34875134444049_kernel(const float* __restrict__ rep_f,
                                            const float* __restrict__ dmask_f,
                                            const float* __restrict__ pmask_f,
                                            const int* __restrict__ lowp,
                                            const int* __restrict__ upp,
                                            float* __restrict__ out_f)
{
    const int gid = blockIdx.x * BLK + threadIdx.x;   // 0 .. B*TP-1 (pair id)
    const int b  = gid >> 11;                         // TP = 2048
    const int tp = gid & (TP - 1);
    const int base = b * (D_DIM * TP) + tp;           // u64 index

    const u64* __restrict__ rep = (const u64*)rep_f + base;
    const u64* __restrict__ dmb = (const u64*)dmask_f + base;
    const u64* __restrict__ pmb = (const u64*)pmask_f + base;

    const int low = *lowp;
    const int up  = *upp;

    // pm[63] is dead (fine terms reach pm[61], coarse reach pm[62])
    u64 pmv[63];
#pragma unroll
    for (int w = 0; w < 63; w++) pmv[w] = pmb[w * TP];

    u64 res = 0ULL;

    u64 L1[32]; transition<32, TP, TP>(rep, L1, pmv, dmb, low, up, res);
    u64 L2[16]; transition<16, 1, TP>(L1, L2, pmv, dmb, low, up, res);
    u64 L3[8];  transition<8, 1, TP>(L2, L3, pmv, dmb, low, up, res);
    u64 L4[4];  transition<4, 1, TP>(L3, L4, pmv, dmb, low, up, res);
    u64 L5[2];  transition<2, 1, TP>(L4, L5, pmv, dmb, low, up, res);

    // W = 1: d = deepest level (single packed element)
    const u64 x6 = mul2(HALF2, add2(L5[0], L5[1]));
    if (1 >= low && 1 < up) res = fma2(dmb[0], mul2(x6, pmv[0]), res);

    ((u64*)out_f)[gid] = res;   // two adjacent t outputs
}

extern "C" void kernel_launch(void* const* d_in, const int* in_sizes, int n_in,
                              void* d_out, int out_size)
{
    const float* rep   = (const float*)d_in[0];
    const float* dmask = (const float*)d_in[1];
    const float* pmask = (const float*)d_in[2];
    const int*   lowp  = (const int*)d_in[3];
    const int*   upp   = (const int*)d_in[4];
    float* out = (float*)d_out;

    const int pairs = B_DIM * TP;              // 65536
    ContextGenerator_34875134444049_kernel<<<pairs / BLK, BLK>>>(
        rep, dmask, pmask, lowp, upp, out);
}